// round 1
// baseline (speedup 1.0000x reference)
#include <cuda_runtime.h>
#include <cuda_bf16.h>
#include <math.h>

// Problem constants
#define BATCH 2
#define SEQ   2048
#define DMODEL 1024
#define NHEAD 16
#define HD    64
#define MTOT  (BATCH*SEQ)        // 4096 rows for projections

// ---------------- scratch (no allocations allowed) ----------------
__device__ float g_q[BATCH*SEQ*DMODEL];
__device__ float g_k[BATCH*SEQ*DMODEL];
__device__ float g_v[BATCH*SEQ*DMODEL];
__device__ float g_attn[BATCH*SEQ*DMODEL];

// ---------------- GEMM: C[M,N] = A[M,K] @ W[N,K]^T + bias[N] ----------------
// A row-major [M,K], W row-major [N,K] (torch Linear weight), both K-contiguous.
#define BM 128
#define BN 128
#define BKG 16
#define GSTR (BM + 4)

__global__ __launch_bounds__(256) void gemm_nt_bias(
    const float* __restrict__ A, const float* __restrict__ W,
    const float* __restrict__ bias, float* __restrict__ C,
    int M, int N, int K)
{
    __shared__ float As[BKG][GSTR];
    __shared__ float Ws[BKG][GSTR];

    const int tid = threadIdx.x;
    const int tx = tid & 15;       // col group
    const int ty = tid >> 4;       // row group
    const int m0 = blockIdx.y * BM;
    const int n0 = blockIdx.x * BN;

    float acc[8][8];
#pragma unroll
    for (int i = 0; i < 8; i++)
#pragma unroll
        for (int j = 0; j < 8; j++) acc[i][j] = 0.f;

    for (int k0 = 0; k0 < K; k0 += BKG) {
        // Load A tile (128x16) and W tile (128x16), transposed into smem.
#pragma unroll
        for (int l = 0; l < 2; l++) {
            int f4  = tid + l * 256;          // 512 float4 per tile
            int row = f4 >> 2;                // 0..127
            int kk  = (f4 & 3) * 4;           // 0,4,8,12
            float4 a = *(const float4*)&A[(size_t)(m0 + row) * K + k0 + kk];
            As[kk+0][row] = a.x; As[kk+1][row] = a.y;
            As[kk+2][row] = a.z; As[kk+3][row] = a.w;
            float4 w = *(const float4*)&W[(size_t)(n0 + row) * K + k0 + kk];
            Ws[kk+0][row] = w.x; Ws[kk+1][row] = w.y;
            Ws[kk+2][row] = w.z; Ws[kk+3][row] = w.w;
        }
        __syncthreads();

#pragma unroll
        for (int kk = 0; kk < BKG; kk++) {
            float a[8], b[8];
            *(float4*)&a[0] = *(const float4*)&As[kk][ty * 8];
            *(float4*)&a[4] = *(const float4*)&As[kk][ty * 8 + 4];
            *(float4*)&b[0] = *(const float4*)&Ws[kk][tx * 8];
            *(float4*)&b[4] = *(const float4*)&Ws[kk][tx * 8 + 4];
#pragma unroll
            for (int i = 0; i < 8; i++)
#pragma unroll
                for (int j = 0; j < 8; j++)
                    acc[i][j] = fmaf(a[i], b[j], acc[i][j]);
        }
        __syncthreads();
    }

    // Epilogue: add bias, write float4s
#pragma unroll
    for (int i = 0; i < 8; i++) {
        int row = m0 + ty * 8 + i;
#pragma unroll
        for (int j4 = 0; j4 < 2; j4++) {
            int col = n0 + tx * 8 + j4 * 4;
            float4 o;
            o.x = acc[i][j4*4+0] + bias[col+0];
            o.y = acc[i][j4*4+1] + bias[col+1];
            o.z = acc[i][j4*4+2] + bias[col+2];
            o.w = acc[i][j4*4+3] + bias[col+3];
            *(float4*)&C[(size_t)row * N + col] = o;
        }
    }
}

// ---------------- Flash attention (causal), fp32 ----------------
// One block per (q_tile of 64, head, batch). 256 threads = 16x16,
// each thread owns a 4x4 score/output microtile (rows ty*4.., cols tx*4..).
#define QT 64
#define KT 64
#define SSTR 68   // padded row stride (floats), mult of 4 for float4 smem ops

__global__ __launch_bounds__(256) void attn_kernel(
    const float* __restrict__ Q, const float* __restrict__ Kb,
    const float* __restrict__ Vb, float* __restrict__ O)
{
    extern __shared__ float sm[];
    float* Qs = sm;                 // QT * SSTR
    float* Ks = Qs + QT * SSTR;
    float* Vs = Ks + KT * SSTR;
    float* Ss = Vs + KT * SSTR;     // scores -> P, reused

    const int tid = threadIdx.x;
    const int tx = tid & 15;
    const int ty = tid >> 4;
    const int qtile = blockIdx.x;
    const int h = blockIdx.y;
    const int b = blockIdx.z;

    const int q0 = qtile * QT;
    const size_t base = ((size_t)b * SEQ) * DMODEL + (size_t)h * HD;
    const float scale = 0.125f;     // 1/sqrt(64)

    // Load Q tile (64 rows x 64 dims), pre-scaled
#pragma unroll
    for (int l = 0; l < 4; l++) {
        int f4  = tid + l * 256;     // 1024 float4
        int row = f4 >> 4;
        int col = (f4 & 15) * 4;
        float4 v = *(const float4*)&Q[base + (size_t)(q0 + row) * DMODEL + col];
        float* p = &Qs[row * SSTR + col];
        p[0] = v.x * scale; p[1] = v.y * scale; p[2] = v.z * scale; p[3] = v.w * scale;
    }

    float m[4], lsum[4], acc[4][4];
#pragma unroll
    for (int i = 0; i < 4; i++) {
        m[i] = -1e30f; lsum[i] = 0.f;
#pragma unroll
        for (int j = 0; j < 4; j++) acc[i][j] = 0.f;
    }

    const int ntiles = qtile + 1;   // causal
    for (int jt = 0; jt < ntiles; jt++) {
        __syncthreads();            // protect Ks/Vs from previous iteration readers
        // Load K and V tiles
#pragma unroll
        for (int l = 0; l < 4; l++) {
            int f4  = tid + l * 256;
            int row = f4 >> 4;
            int col = (f4 & 15) * 4;
            size_t g = base + (size_t)(jt * KT + row) * DMODEL + col;
            float4 kv = *(const float4*)&Kb[g];
            float* pk = &Ks[row * SSTR + col];
            pk[0] = kv.x; pk[1] = kv.y; pk[2] = kv.z; pk[3] = kv.w;
            float4 vv = *(const float4*)&Vb[g];
            float* pv = &Vs[row * SSTR + col];
            pv[0] = vv.x; pv[1] = vv.y; pv[2] = vv.z; pv[3] = vv.w;
        }
        __syncthreads();

        // Scores: s[i][j] = Qs[row_i] . Ks[col_j]  (4x4 microtile)
        float s[4][4];
#pragma unroll
        for (int i = 0; i < 4; i++)
#pragma unroll
            for (int j = 0; j < 4; j++) s[i][j] = 0.f;

#pragma unroll
        for (int k4 = 0; k4 < 16; k4++) {
            float4 qa[4], kb4[4];
#pragma unroll
            for (int i = 0; i < 4; i++)
                qa[i] = *(const float4*)&Qs[(ty * 4 + i) * SSTR + k4 * 4];
#pragma unroll
            for (int j = 0; j < 4; j++)
                kb4[j] = *(const float4*)&Ks[(tx * 4 + j) * SSTR + k4 * 4];
#pragma unroll
            for (int i = 0; i < 4; i++)
#pragma unroll
                for (int j = 0; j < 4; j++) {
                    s[i][j] = fmaf(qa[i].x, kb4[j].x, s[i][j]);
                    s[i][j] = fmaf(qa[i].y, kb4[j].y, s[i][j]);
                    s[i][j] = fmaf(qa[i].z, kb4[j].z, s[i][j]);
                    s[i][j] = fmaf(qa[i].w, kb4[j].w, s[i][j]);
                }
        }

        // Causal mask (only the diagonal tile needs it)
        if (jt == qtile) {
#pragma unroll
            for (int i = 0; i < 4; i++)
#pragma unroll
                for (int j = 0; j < 4; j++)
                    if (jt * KT + tx * 4 + j > q0 + ty * 4 + i) s[i][j] = -1e30f;
        }

        // Online softmax: rows owned by the 16-lane tx group (same half-warp)
#pragma unroll
        for (int i = 0; i < 4; i++) {
            float mt = fmaxf(fmaxf(s[i][0], s[i][1]), fmaxf(s[i][2], s[i][3]));
#pragma unroll
            for (int off = 8; off >= 1; off >>= 1)
                mt = fmaxf(mt, __shfl_xor_sync(0xffffffffu, mt, off, 16));
            float mn = fmaxf(m[i], mt);
            float corr = __expf(m[i] - mn);
            float ps = 0.f;
            float4 pvec;
            pvec.x = __expf(s[i][0] - mn);
            pvec.y = __expf(s[i][1] - mn);
            pvec.z = __expf(s[i][2] - mn);
            pvec.w = __expf(s[i][3] - mn);
            ps = pvec.x + pvec.y + pvec.z + pvec.w;
#pragma unroll
            for (int off = 8; off >= 1; off >>= 1)
                ps += __shfl_xor_sync(0xffffffffu, ps, off, 16);
            lsum[i] = lsum[i] * corr + ps;
            m[i] = mn;
#pragma unroll
            for (int j = 0; j < 4; j++) acc[i][j] *= corr;
            *(float4*)&Ss[(ty * 4 + i) * SSTR + tx * 4] = pvec;
        }
        __syncwarp();   // P rows for this ty group are warp-local

        // PV: acc[i][j] += sum_k P[row_i][k] * V[k][col_j]
#pragma unroll
        for (int k4 = 0; k4 < 16; k4++) {
            float pr[4][4];
#pragma unroll
            for (int i = 0; i < 4; i++) {
                float4 t = *(const float4*)&Ss[(ty * 4 + i) * SSTR + k4 * 4];
                pr[i][0] = t.x; pr[i][1] = t.y; pr[i][2] = t.z; pr[i][3] = t.w;
            }
#pragma unroll
            for (int kk = 0; kk < 4; kk++) {
                float4 vv = *(const float4*)&Vs[(k4 * 4 + kk) * SSTR + tx * 4];
#pragma unroll
                for (int i = 0; i < 4; i++) {
                    acc[i][0] = fmaf(pr[i][kk], vv.x, acc[i][0]);
                    acc[i][1] = fmaf(pr[i][kk], vv.y, acc[i][1]);
                    acc[i][2] = fmaf(pr[i][kk], vv.z, acc[i][2]);
                    acc[i][3] = fmaf(pr[i][kk], vv.w, acc[i][3]);
                }
            }
        }
    }

    // Epilogue: normalize and store
#pragma unroll
    for (int i = 0; i < 4; i++) {
        float inv = 1.f / lsum[i];
        int row = q0 + ty * 4 + i;
        float4 o;
        o.x = acc[i][0] * inv; o.y = acc[i][1] * inv;
        o.z = acc[i][2] * inv; o.w = acc[i][3] * inv;
        *(float4*)&O[base + (size_t)row * DMODEL + tx * 4] = o;
    }
}

// ---------------- launch ----------------
extern "C" void kernel_launch(void* const* d_in, const int* in_sizes, int n_in,
                              void* d_out, int out_size)
{
    const float* x  = (const float*)d_in[0];
    const float* wq = (const float*)d_in[1];
    const float* bq = (const float*)d_in[2];
    const float* wk = (const float*)d_in[3];
    const float* bk = (const float*)d_in[4];
    const float* wv = (const float*)d_in[5];
    const float* bv = (const float*)d_in[6];
    const float* wo = (const float*)d_in[7];
    const float* bo = (const float*)d_in[8];
    float* out = (float*)d_out;

    float *qb, *kb, *vb, *ab;
    cudaGetSymbolAddress((void**)&qb, g_q);
    cudaGetSymbolAddress((void**)&kb, g_k);
    cudaGetSymbolAddress((void**)&vb, g_v);
    cudaGetSymbolAddress((void**)&ab, g_attn);

    dim3 gdim(DMODEL / BN, MTOT / BM);   // (8, 32)
    gemm_nt_bias<<<gdim, 256>>>(x, wq, bq, qb, MTOT, DMODEL, DMODEL);
    gemm_nt_bias<<<gdim, 256>>>(x, wk, bk, kb, MTOT, DMODEL, DMODEL);
    gemm_nt_bias<<<gdim, 256>>>(x, wv, bv, vb, MTOT, DMODEL, DMODEL);

    const int smem_attn = 4 * QT * SSTR * (int)sizeof(float);  // ~68 KB
    cudaFuncSetAttribute(attn_kernel, cudaFuncAttributeMaxDynamicSharedMemorySize, smem_attn);
    attn_kernel<<<dim3(SEQ / QT, NHEAD, BATCH), 256, smem_attn>>>(qb, kb, vb, ab);

    gemm_nt_bias<<<gdim, 256>>>(ab, wo, bo, out, MTOT, DMODEL, DMODEL);
}

// round 5
// speedup vs baseline: 3.5032x; 3.5032x over previous
#include <cuda_runtime.h>
#include <cuda_bf16.h>
#include <math.h>

typedef unsigned int u32;   // avoid any <cstdint> dependency

// Problem constants
#define BATCH 2
#define SEQ   2048
#define DMODEL 1024
#define NHEAD 16
#define HD    64
#define MTOT  (BATCH*SEQ)

// ---------------- scratch ----------------
__device__ float g_q[BATCH*SEQ*DMODEL];
__device__ float g_k[BATCH*SEQ*DMODEL];
__device__ float g_v[BATCH*SEQ*DMODEL];
__device__ float g_attn[BATCH*SEQ*DMODEL];

// ---------------- helpers ----------------
__device__ __forceinline__ u32 f2tf(float x) {
    u32 u;
    asm("cvt.rna.tf32.f32 %0, %1;" : "=r"(u) : "f"(x));
    return u;
}
__device__ __forceinline__ float tfbits(float x) {  // tf32-round, keep as float bits
    return __uint_as_float(f2tf(x));
}
__device__ __forceinline__ void mma_tf32(float* d, const u32* a, const u32* b) {
    asm volatile(
        "mma.sync.aligned.m16n8k8.row.col.f32.tf32.tf32.f32 "
        "{%0,%1,%2,%3},{%4,%5,%6,%7},{%8,%9},{%0,%1,%2,%3};"
        : "+f"(d[0]), "+f"(d[1]), "+f"(d[2]), "+f"(d[3])
        : "r"(a[0]), "r"(a[1]), "r"(a[2]), "r"(a[3]), "r"(b[0]), "r"(b[1]));
}
__device__ __forceinline__ u32 ldsu(const float* p) {
    return __float_as_uint(*p);
}

// ---------------- GEMM: C[M,N] = A[M,K] @ W[N,K]^T + bias[N] (tf32 mma) ----------------
// Block 128x128, BK=32. 8 warps in 2(M) x 4(N); warp tile 64x32.
#define GBM 128
#define GBN 128
#define GBK 32
#define GASTR 36   // 36 mod 32 == 4 -> conflict-free fragment LDS

__global__ __launch_bounds__(256, 2) void gemm_nt_bias(
    const float* __restrict__ A, const float* __restrict__ W,
    const float* __restrict__ bias, float* __restrict__ C,
    int M, int N, int K)
{
    __shared__ float As[GBM * GASTR];
    __shared__ float Ws[GBM * GASTR];

    const int tid  = threadIdx.x;
    const int warp = tid >> 5;
    const int lane = tid & 31;
    const int g    = lane >> 2;   // group id 0..7
    const int t4   = lane & 3;    // thread-in-group 0..3
    const int wm   = warp >> 2;   // 0..1
    const int wn   = warp & 3;    // 0..3
    const int m0   = blockIdx.y * GBM;
    const int n0   = blockIdx.x * GBN;

    float acc[4][4][4];
#pragma unroll
    for (int i = 0; i < 4; i++)
#pragma unroll
        for (int j = 0; j < 4; j++)
#pragma unroll
            for (int r = 0; r < 4; r++) acc[i][j][r] = 0.f;

    // register stage for global prefetch: 4 float4 per tile per thread
    float4 ar[4], wr4[4];
    const int srow[4] = { (tid + 0)   >> 3, (tid + 256) >> 3,
                          (tid + 512) >> 3, (tid + 768) >> 3 };
    const int skq = (tid & 7) * 4;

    // prologue load k0 = 0
#pragma unroll
    for (int l = 0; l < 4; l++) {
        ar[l]  = *(const float4*)&A[(size_t)(m0 + srow[l]) * K + skq];
        wr4[l] = *(const float4*)&W[(size_t)(n0 + srow[l]) * K + skq];
    }

    const int NKB = K / GBK;
    for (int kb = 0; kb < NKB; kb++) {
        // store stage to smem with tf32 rounding
#pragma unroll
        for (int l = 0; l < 4; l++) {
            float4 a4, w4;
            a4.x = tfbits(ar[l].x); a4.y = tfbits(ar[l].y);
            a4.z = tfbits(ar[l].z); a4.w = tfbits(ar[l].w);
            w4.x = tfbits(wr4[l].x); w4.y = tfbits(wr4[l].y);
            w4.z = tfbits(wr4[l].z); w4.w = tfbits(wr4[l].w);
            *(float4*)&As[srow[l] * GASTR + skq] = a4;
            *(float4*)&Ws[srow[l] * GASTR + skq] = w4;
        }
        __syncthreads();

        // prefetch next tile
        if (kb + 1 < NKB) {
            int k0 = (kb + 1) * GBK;
#pragma unroll
            for (int l = 0; l < 4; l++) {
                ar[l]  = *(const float4*)&A[(size_t)(m0 + srow[l]) * K + k0 + skq];
                wr4[l] = *(const float4*)&W[(size_t)(n0 + srow[l]) * K + k0 + skq];
            }
        }

        // compute 4 k-steps of 8
#pragma unroll
        for (int ks = 0; ks < 4; ks++) {
            const int k = ks * 8;
            u32 af[4][4], bf[4][2];
#pragma unroll
            for (int i = 0; i < 4; i++) {
                int rb = wm * 64 + i * 16 + g;
                af[i][0] = ldsu(&As[(rb)     * GASTR + k + t4]);
                af[i][1] = ldsu(&As[(rb + 8) * GASTR + k + t4]);
                af[i][2] = ldsu(&As[(rb)     * GASTR + k + t4 + 4]);
                af[i][3] = ldsu(&As[(rb + 8) * GASTR + k + t4 + 4]);
            }
#pragma unroll
            for (int j = 0; j < 4; j++) {
                int nb = wn * 32 + j * 8 + g;
                bf[j][0] = ldsu(&Ws[nb * GASTR + k + t4]);
                bf[j][1] = ldsu(&Ws[nb * GASTR + k + t4 + 4]);
            }
#pragma unroll
            for (int i = 0; i < 4; i++)
#pragma unroll
                for (int j = 0; j < 4; j++)
                    mma_tf32(acc[i][j], af[i], bf[j]);
        }
        __syncthreads();
    }

    // epilogue: bias + store
#pragma unroll
    for (int j = 0; j < 4; j++) {
        int col = n0 + wn * 32 + j * 8 + 2 * t4;
        float b0 = bias[col], b1 = bias[col + 1];
#pragma unroll
        for (int i = 0; i < 4; i++) {
            int r0 = m0 + wm * 64 + i * 16 + g;
            float2 o0 = { acc[i][j][0] + b0, acc[i][j][1] + b1 };
            float2 o1 = { acc[i][j][2] + b0, acc[i][j][3] + b1 };
            *(float2*)&C[(size_t)r0 * N + col]       = o0;
            *(float2*)&C[(size_t)(r0 + 8) * N + col] = o1;
        }
    }
}

// ---------------- Flash attention (causal), tf32 mma ----------------
// QT=128 rows per block, 8 warps (16 rows each), KT=64.
#define AQT 128
#define AKT 64
#define KSTR 68   // [n][k] pattern, 68 mod 32 == 4 -> conflict-free
#define VSTR 72   // [k][n] pattern, 72 mod 32 == 8 -> conflict-free
#define PSTR 68

#define SM_K  0
#define SM_V  (AKT * KSTR)               // 4352
#define SM_Q  (SM_V + AKT * VSTR)        // 8960
#define SM_P  (SM_Q + AQT * PSTR)        // 17664
#define SM_FL (SM_P + AQT * PSTR)        // 26368 floats = 105472 B

__global__ __launch_bounds__(256, 2) void attn_kernel(
    const float* __restrict__ Q, const float* __restrict__ Kb,
    const float* __restrict__ Vb, float* __restrict__ O)
{
    extern __shared__ float sm[];
    float* Ks = sm + SM_K;
    float* Vs = sm + SM_V;
    float* Qs = sm + SM_Q;
    float* Ps = sm + SM_P;

    const int tid  = threadIdx.x;
    const int warp = tid >> 5;
    const int lane = tid & 31;
    const int g    = lane >> 2;
    const int t4   = lane & 3;

    const int qtile = (int)gridDim.x - 1 - (int)blockIdx.x;  // heavy tiles first
    const int h = blockIdx.y;
    const int b = blockIdx.z;
    const int q0 = qtile * AQT;
    const size_t base = ((size_t)b * SEQ) * DMODEL + (size_t)h * HD;
    const float scale = 0.125f;

    // Load Q tile (128 x 64), pre-scaled, tf32-rounded
#pragma unroll
    for (int l = 0; l < 8; l++) {
        int f4  = tid + l * 256;
        int row = f4 >> 4;
        int col = (f4 & 15) * 4;
        float4 v = *(const float4*)&Q[base + (size_t)(q0 + row) * DMODEL + col];
        float4 o;
        o.x = tfbits(v.x * scale); o.y = tfbits(v.y * scale);
        o.z = tfbits(v.z * scale); o.w = tfbits(v.w * scale);
        *(float4*)&Qs[row * PSTR + col] = o;
    }

    float of[8][4];
#pragma unroll
    for (int j = 0; j < 8; j++)
#pragma unroll
        for (int r = 0; r < 4; r++) of[j][r] = 0.f;
    float m0r = -1e30f, m1r = -1e30f, l0r = 0.f, l1r = 0.f;

    const int w16 = warp * 16;
    const int ntiles = 2 * qtile + 2;

    for (int jt = 0; jt < ntiles; jt++) {
        __syncthreads();   // previous readers of Ks/Vs done (also covers Q store, iter 0)
        // Load K and V tiles (64 x 64 each)
#pragma unroll
        for (int l = 0; l < 4; l++) {
            int f4  = tid + l * 256;
            int row = f4 >> 4;
            int col = (f4 & 15) * 4;
            size_t gaddr = base + (size_t)(jt * AKT + row) * DMODEL + col;
            float4 kv = *(const float4*)&Kb[gaddr];
            float4 ko;
            ko.x = tfbits(kv.x); ko.y = tfbits(kv.y);
            ko.z = tfbits(kv.z); ko.w = tfbits(kv.w);
            *(float4*)&Ks[row * KSTR + col] = ko;
            float4 vv = *(const float4*)&Vb[gaddr];
            float4 vo;
            vo.x = tfbits(vv.x); vo.y = tfbits(vv.y);
            vo.z = tfbits(vv.z); vo.w = tfbits(vv.w);
            *(float4*)&Vs[row * VSTR + col] = vo;
        }
        __syncthreads();

        // ---- S = Q @ K^T ----
        float s[8][4];
#pragma unroll
        for (int j = 0; j < 8; j++)
#pragma unroll
            for (int r = 0; r < 4; r++) s[j][r] = 0.f;

#pragma unroll
        for (int ks = 0; ks < 8; ks++) {
            const int k = ks * 8;
            u32 a[4];
            a[0] = ldsu(&Qs[(w16 + g)     * PSTR + k + t4]);
            a[1] = ldsu(&Qs[(w16 + g + 8) * PSTR + k + t4]);
            a[2] = ldsu(&Qs[(w16 + g)     * PSTR + k + t4 + 4]);
            a[3] = ldsu(&Qs[(w16 + g + 8) * PSTR + k + t4 + 4]);
#pragma unroll
            for (int j = 0; j < 8; j++) {
                u32 bfr[2];
                bfr[0] = ldsu(&Ks[(j * 8 + g) * KSTR + k + t4]);
                bfr[1] = ldsu(&Ks[(j * 8 + g) * KSTR + k + t4 + 4]);
                mma_tf32(s[j], a, bfr);
            }
        }

        // ---- causal mask (diagonal tiles only) ----
        if (jt >= 2 * qtile) {
            int r0 = q0 + w16 + g, r1 = r0 + 8;
#pragma unroll
            for (int j = 0; j < 8; j++) {
                int c = jt * AKT + j * 8 + 2 * t4;
                if (c     > r0) s[j][0] = -1e30f;
                if (c + 1 > r0) s[j][1] = -1e30f;
                if (c     > r1) s[j][2] = -1e30f;
                if (c + 1 > r1) s[j][3] = -1e30f;
            }
        }

        // ---- online softmax ----
        float mt0 = -1e30f, mt1 = -1e30f;
#pragma unroll
        for (int j = 0; j < 8; j++) {
            mt0 = fmaxf(mt0, fmaxf(s[j][0], s[j][1]));
            mt1 = fmaxf(mt1, fmaxf(s[j][2], s[j][3]));
        }
        mt0 = fmaxf(mt0, __shfl_xor_sync(0xffffffffu, mt0, 1));
        mt0 = fmaxf(mt0, __shfl_xor_sync(0xffffffffu, mt0, 2));
        mt1 = fmaxf(mt1, __shfl_xor_sync(0xffffffffu, mt1, 1));
        mt1 = fmaxf(mt1, __shfl_xor_sync(0xffffffffu, mt1, 2));

        float mn0 = fmaxf(m0r, mt0), mn1 = fmaxf(m1r, mt1);
        float corr0 = __expf(m0r - mn0), corr1 = __expf(m1r - mn1);
        m0r = mn0; m1r = mn1;

        float ps0 = 0.f, ps1 = 0.f;
#pragma unroll
        for (int j = 0; j < 8; j++) {
            s[j][0] = __expf(s[j][0] - mn0); ps0 += s[j][0];
            s[j][1] = __expf(s[j][1] - mn0); ps0 += s[j][1];
            s[j][2] = __expf(s[j][2] - mn1); ps1 += s[j][2];
            s[j][3] = __expf(s[j][3] - mn1); ps1 += s[j][3];
        }
        ps0 += __shfl_xor_sync(0xffffffffu, ps0, 1);
        ps0 += __shfl_xor_sync(0xffffffffu, ps0, 2);
        ps1 += __shfl_xor_sync(0xffffffffu, ps1, 1);
        ps1 += __shfl_xor_sync(0xffffffffu, ps1, 2);
        l0r = l0r * corr0 + ps0;
        l1r = l1r * corr1 + ps1;

#pragma unroll
        for (int j = 0; j < 8; j++) {
            of[j][0] *= corr0; of[j][1] *= corr0;
            of[j][2] *= corr1; of[j][3] *= corr1;
        }

        // store P (tf32) to warp-private smem rows
#pragma unroll
        for (int j = 0; j < 8; j++) {
            int rr = w16 + g, col = j * 8 + 2 * t4;
            Ps[rr * PSTR + col]           = tfbits(s[j][0]);
            Ps[rr * PSTR + col + 1]       = tfbits(s[j][1]);
            Ps[(rr + 8) * PSTR + col]     = tfbits(s[j][2]);
            Ps[(rr + 8) * PSTR + col + 1] = tfbits(s[j][3]);
        }
        __syncwarp();

        // ---- O += P @ V ----
#pragma unroll
        for (int ks = 0; ks < 8; ks++) {
            const int k = ks * 8;
            u32 pa[4];
            pa[0] = ldsu(&Ps[(w16 + g)     * PSTR + k + t4]);
            pa[1] = ldsu(&Ps[(w16 + g + 8) * PSTR + k + t4]);
            pa[2] = ldsu(&Ps[(w16 + g)     * PSTR + k + t4 + 4]);
            pa[3] = ldsu(&Ps[(w16 + g + 8) * PSTR + k + t4 + 4]);
#pragma unroll
            for (int j = 0; j < 8; j++) {
                u32 bfr[2];
                bfr[0] = ldsu(&Vs[(k + t4)     * VSTR + j * 8 + g]);
                bfr[1] = ldsu(&Vs[(k + t4 + 4) * VSTR + j * 8 + g]);
                mma_tf32(of[j], pa, bfr);
            }
        }
        __syncwarp();   // all lanes done reading Ps before next tile overwrites
    }

    // ---- epilogue ----
    float inv0 = 1.f / l0r, inv1 = 1.f / l1r;
    int r0 = q0 + w16 + g, r1 = r0 + 8;
#pragma unroll
    for (int j = 0; j < 8; j++) {
        int col = j * 8 + 2 * t4;
        float2 o0 = { of[j][0] * inv0, of[j][1] * inv0 };
        float2 o1 = { of[j][2] * inv1, of[j][3] * inv1 };
        *(float2*)&O[base + (size_t)r0 * DMODEL + col] = o0;
        *(float2*)&O[base + (size_t)r1 * DMODEL + col] = o1;
    }
}

// ---------------- launch ----------------
extern "C" void kernel_launch(void* const* d_in, const int* in_sizes, int n_in,
                              void* d_out, int out_size)
{
    const float* x  = (const float*)d_in[0];
    const float* wq = (const float*)d_in[1];
    const float* bq = (const float*)d_in[2];
    const float* wk = (const float*)d_in[3];
    const float* bk = (const float*)d_in[4];
    const float* wv = (const float*)d_in[5];
    const float* bv = (const float*)d_in[6];
    const float* wo = (const float*)d_in[7];
    const float* bo = (const float*)d_in[8];
    float* out = (float*)d_out;

    float *qb, *kb, *vb, *ab;
    cudaGetSymbolAddress((void**)&qb, g_q);
    cudaGetSymbolAddress((void**)&kb, g_k);
    cudaGetSymbolAddress((void**)&vb, g_v);
    cudaGetSymbolAddress((void**)&ab, g_attn);

    dim3 gdim(DMODEL / GBN, MTOT / GBM);   // (8, 32)
    gemm_nt_bias<<<gdim, 256>>>(x, wq, bq, qb, MTOT, DMODEL, DMODEL);
    gemm_nt_bias<<<gdim, 256>>>(x, wk, bk, kb, MTOT, DMODEL, DMODEL);
    gemm_nt_bias<<<gdim, 256>>>(x, wv, bv, vb, MTOT, DMODEL, DMODEL);

    const int smem_attn = SM_FL * (int)sizeof(float);   // 105472 B
    cudaFuncSetAttribute(attn_kernel, cudaFuncAttributeMaxDynamicSharedMemorySize, smem_attn);
    attn_kernel<<<dim3(SEQ / AQT, NHEAD, BATCH), 256, smem_attn>>>(qb, kb, vb, ab);

    gemm_nt_bias<<<gdim, 256>>>(ab, wo, bo, out, MTOT, DMODEL, DMODEL);
}